// round 1
// baseline (speedup 1.0000x reference)
#include <cuda_runtime.h>
#include <cstdint>

#define NQ 32
#define NS 25
#define NL 64
#define NF 256
#define NH 64

// Scratch (allocation-free rule: __device__ globals)
__device__ float g_WT[NF * NH];        // W transposed: [f][h]
__device__ float g_WqT[NQ * NH * NL];  // per q: [h][i]
__device__ float g_WhT[NS * NH * NL];  // per s: [h][j]

__device__ __forceinline__ float fast_ex2(float x) {
    float r; asm("ex2.approx.f32 %0, %1;" : "=f"(r) : "f"(x)); return r;
}
__device__ __forceinline__ float fast_rcp(float x) {
    float r; asm("rcp.approx.f32 %0, %1;" : "=f"(r) : "f"(x)); return r;
}
// tanh(x) = 1 - 2/(exp(2x)+1); accurate to ~1e-6 abs (ex2/rcp approx are ~1ulp)
__device__ __forceinline__ float fast_tanh(float x) {
    float e = fast_ex2(x * 2.8853900817779268f);  // 2*log2(e)
    float r = fast_rcp(e + 1.0f);
    return fmaf(-2.0f, r, 1.0f);
}

// K0: transpose W [H][F] -> g_WT [F][H]  (one-time, tiny)
__global__ void k_transpose_W(const float* __restrict__ W) {
    int t = blockIdx.x * blockDim.x + threadIdx.x;
    for (int e = t; e < NF * NH; e += blockDim.x * gridDim.x) {
        int h = e >> 8;          // e / NF
        int f = e & (NF - 1);    // e % NF
        g_WT[f * NH + h] = W[e];
    }
}

// K1: projection. Block b < NQ handles qs[b], else hs[b-NQ].
// Computes dst[h][l] = sum_f x[l][f] * W[h][f] + bias[h], stored h-major.
__global__ __launch_bounds__(256) void k_project(const float* __restrict__ qs,
                                                 const float* __restrict__ hs,
                                                 const float* __restrict__ bias) {
    extern __shared__ float sm[];
    float* xs = sm;              // [NL][NF]
    float* wT = sm + NL * NF;    // [NF][NH]
    const int b = blockIdx.x;
    const int t = threadIdx.x;
    const float* x = (b < NQ) ? (qs + (size_t)b * NL * NF)
                              : (hs + (size_t)(b - NQ) * NL * NF);
    float* dst = (b < NQ) ? (g_WqT + (size_t)b * NH * NL)
                          : (g_WhT + (size_t)(b - NQ) * NH * NL);

    {
        const float4* xg = reinterpret_cast<const float4*>(x);
        float4* xs4 = reinterpret_cast<float4*>(xs);
        for (int e = t; e < NL * NF / 4; e += 256) xs4[e] = xg[e];
        const float4* wg = reinterpret_cast<const float4*>(g_WT);
        float4* ws4 = reinterpret_cast<float4*>(wT);
        for (int e = t; e < NF * NH / 4; e += 256) ws4[e] = wg[e];
    }
    __syncthreads();

    const int h0 = 4 * (t & 15);   // wT loads coalesced over h
    const int l0 = 4 * (t >> 4);   // xs loads broadcast (2 addrs/warp)
    float acc[4][4];               // [c = h-rel][r = l-rel]
    #pragma unroll
    for (int c = 0; c < 4; c++)
        #pragma unroll
        for (int r = 0; r < 4; r++) acc[c][r] = 0.f;

    for (int f = 0; f < NF; f += 4) {
        float xv[4][4];  // [r][i]
        #pragma unroll
        for (int r = 0; r < 4; r++) {
            float4 v = *reinterpret_cast<const float4*>(&xs[(l0 + r) * NF + f]);
            xv[r][0] = v.x; xv[r][1] = v.y; xv[r][2] = v.z; xv[r][3] = v.w;
        }
        #pragma unroll
        for (int i = 0; i < 4; i++) {
            float4 w = *reinterpret_cast<const float4*>(&wT[(f + i) * NH + h0]);
            float wv[4] = {w.x, w.y, w.z, w.w};
            #pragma unroll
            for (int c = 0; c < 4; c++)
                #pragma unroll
                for (int r = 0; r < 4; r++)
                    acc[c][r] = fmaf(wv[c], xv[r][i], acc[c][r]);
        }
    }
    #pragma unroll
    for (int c = 0; c < 4; c++) {
        float bb = __ldg(&bias[h0 + c]);
        float4 v = make_float4(acc[c][0] + bb, acc[c][1] + bb,
                               acc[c][2] + bb, acc[c][3] + bb);
        *reinterpret_cast<float4*>(&dst[(h0 + c) * NL + l0]) = v;
    }
}

// K2: fused scores(tanh) -> softmax -> att @ hs, one block per (q, s).
__global__ __launch_bounds__(256) void k_attn(const float* __restrict__ hs,
                                              float* __restrict__ out) {
    extern __shared__ float sm[];
    float* wqT = sm;                 // [NH][NL]  4096 f
    float* whT = sm + NH * NL;       // [NH][NL]  4096 f
    float* hss = sm + 2 * NH * NL;   // [NL][NF] 16384 f
    float* attT = sm;                // overlay over wqT: [j][i] stride NL

    const int s = blockIdx.x;
    const int q = blockIdx.y;
    const int t = threadIdx.x;

    {
        const float4* a = reinterpret_cast<const float4*>(g_WqT + (size_t)q * NH * NL);
        const float4* b = reinterpret_cast<const float4*>(g_WhT + (size_t)s * NH * NL);
        const float4* c = reinterpret_cast<const float4*>(hs + (size_t)s * NL * NF);
        float4* w1 = reinterpret_cast<float4*>(wqT);
        float4* w2 = reinterpret_cast<float4*>(whT);
        float4* w3 = reinterpret_cast<float4*>(hss);
        for (int e = t; e < NH * NL / 4; e += 256) { w1[e] = a[e]; w2[e] = b[e]; }
        for (int e = t; e < NL * NF / 4; e += 256) w3[e] = c[e];
    }
    __syncthreads();

    const int i0 = 4 * (t >> 4);   // query rows (broadcast loads)
    const int j0 = 4 * (t & 15);   // support cols (coalesced loads)

    // Phase A: scores[i0+r][j0+c] = sum_h tanh(wq[i][h]*wh[j][h])
    float acc[4][4];
    #pragma unroll
    for (int r = 0; r < 4; r++)
        #pragma unroll
        for (int c = 0; c < 4; c++) acc[r][c] = 0.f;

    #pragma unroll 4
    for (int h = 0; h < NH; h++) {
        float4 a4 = *reinterpret_cast<const float4*>(&wqT[h * NL + i0]);
        float4 b4 = *reinterpret_cast<const float4*>(&whT[h * NL + j0]);
        float av[4] = {a4.x, a4.y, a4.z, a4.w};
        float bv[4] = {b4.x, b4.y, b4.z, b4.w};
        #pragma unroll
        for (int r = 0; r < 4; r++)
            #pragma unroll
            for (int c = 0; c < 4; c++)
                acc[r][c] += fast_tanh(av[r] * bv[c]);
    }

    // Phase B: softmax over j for each row. Rows live across 16-lane groups.
    float inv[4];
    #pragma unroll
    for (int r = 0; r < 4; r++) {
        float m = fmaxf(fmaxf(acc[r][0], acc[r][1]), fmaxf(acc[r][2], acc[r][3]));
        #pragma unroll
        for (int d = 1; d < 16; d <<= 1)
            m = fmaxf(m, __shfl_xor_sync(0xffffffffu, m, d));
        float ssum = 0.f;
        #pragma unroll
        for (int c = 0; c < 4; c++) {
            float e = fast_ex2((acc[r][c] - m) * 1.4426950408889634f);
            acc[r][c] = e;
            ssum += e;
        }
        #pragma unroll
        for (int d = 1; d < 16; d <<= 1)
            ssum += __shfl_xor_sync(0xffffffffu, ssum, d);
        inv[r] = fast_rcp(ssum);
    }

    __syncthreads();  // all phase-A reads of wqT/whT done before overlay write
    #pragma unroll
    for (int c = 0; c < 4; c++)
        #pragma unroll
        for (int r = 0; r < 4; r++)
            attT[(j0 + c) * NL + (i0 + r)] = acc[r][c] * inv[r];
    __syncthreads();

    // Phase C: out[i][f] = sum_j att[i][j] * hs[j][f]
    float* op = out + (size_t)((q * NS + s) * NL) * NF;
    #pragma unroll
    for (int p = 0; p < 4; p++) {
        const int fb = 4 * (t & 15) + 64 * p;
        float4 o0 = {0.f, 0.f, 0.f, 0.f}, o1 = o0, o2 = o0, o3 = o0;
        #pragma unroll 4
        for (int j = 0; j < NL; j++) {
            float4 a4 = *reinterpret_cast<const float4*>(&attT[j * NL + i0]);
            float4 hv = *reinterpret_cast<const float4*>(&hss[j * NF + fb]);
            o0.x = fmaf(a4.x, hv.x, o0.x); o0.y = fmaf(a4.x, hv.y, o0.y);
            o0.z = fmaf(a4.x, hv.z, o0.z); o0.w = fmaf(a4.x, hv.w, o0.w);
            o1.x = fmaf(a4.y, hv.x, o1.x); o1.y = fmaf(a4.y, hv.y, o1.y);
            o1.z = fmaf(a4.y, hv.z, o1.z); o1.w = fmaf(a4.y, hv.w, o1.w);
            o2.x = fmaf(a4.z, hv.x, o2.x); o2.y = fmaf(a4.z, hv.y, o2.y);
            o2.z = fmaf(a4.z, hv.z, o2.z); o2.w = fmaf(a4.z, hv.w, o2.w);
            o3.x = fmaf(a4.w, hv.x, o3.x); o3.y = fmaf(a4.w, hv.y, o3.y);
            o3.z = fmaf(a4.w, hv.z, o3.z); o3.w = fmaf(a4.w, hv.w, o3.w);
        }
        *reinterpret_cast<float4*>(&op[(i0 + 0) * NF + fb]) = o0;
        *reinterpret_cast<float4*>(&op[(i0 + 1) * NF + fb]) = o1;
        *reinterpret_cast<float4*>(&op[(i0 + 2) * NF + fb]) = o2;
        *reinterpret_cast<float4*>(&op[(i0 + 3) * NF + fb]) = o3;
    }
}

extern "C" void kernel_launch(void* const* d_in, const int* in_sizes, int n_in,
                              void* d_out, int out_size) {
    const float* qs = (const float*)d_in[0];
    const float* hs = (const float*)d_in[1];
    const float* W  = (const float*)d_in[2];
    const float* b  = (const float*)d_in[3];
    float* out = (float*)d_out;

    const int smem_proj = (NL * NF + NF * NH) * (int)sizeof(float);     // 128 KB
    const int smem_attn = (2 * NH * NL + NL * NF) * (int)sizeof(float); // 96 KB
    cudaFuncSetAttribute(k_project, cudaFuncAttributeMaxDynamicSharedMemorySize, smem_proj);
    cudaFuncSetAttribute(k_attn, cudaFuncAttributeMaxDynamicSharedMemorySize, smem_attn);

    k_transpose_W<<<16, 256>>>(W);
    k_project<<<NQ + NS, 256, smem_proj>>>(qs, hs, b);
    k_attn<<<dim3(NS, NQ), 256, smem_attn>>>(hs, out);
}

// round 2
// speedup vs baseline: 1.0835x; 1.0835x over previous
#include <cuda_runtime.h>
#include <cstdint>

#define NQ 32
#define NS 25
#define NL 64
#define NF 256
#define NH 64

// Scratch (allocation-free rule: __device__ globals)
__device__ float g_WT[NF * NH];        // W transposed: [f][h]
__device__ float g_WqT[NQ * NH * NL];  // per q: [h][i], prescaled later at smem load
__device__ float g_WhT[NS * NH * NL];  // per s: [h][j]

typedef unsigned long long u64;

__device__ __forceinline__ float fast_ex2(float x) {
    float r; asm("ex2.approx.f32 %0, %1;" : "=f"(r) : "f"(x)); return r;
}
__device__ __forceinline__ float fast_rcp(float x) {
    float r; asm("rcp.approx.f32 %0, %1;" : "=f"(r) : "f"(x)); return r;
}
// ---- packed f32x2 ops (sm_103a FFMA2/FMUL2/FADD2) ----
__device__ __forceinline__ u64 f2mul(u64 a, u64 b) {
    u64 r; asm("mul.rn.f32x2 %0, %1, %2;" : "=l"(r) : "l"(a), "l"(b)); return r;
}
__device__ __forceinline__ u64 f2add(u64 a, u64 b) {
    u64 r; asm("add.rn.f32x2 %0, %1, %2;" : "=l"(r) : "l"(a), "l"(b)); return r;
}
__device__ __forceinline__ u64 f2fma(u64 a, u64 b, u64 c) {
    u64 r; asm("fma.rn.f32x2 %0, %1, %2, %3;" : "=l"(r) : "l"(a), "l"(b), "l"(c)); return r;
}
__device__ __forceinline__ u64 pk(float lo, float hi) {
    u64 r; asm("mov.b64 %0, {%1, %2};" : "=l"(r) : "f"(lo), "f"(hi)); return r;
}
__device__ __forceinline__ float2 upk(u64 v) {
    float lo, hi; asm("mov.b64 {%0, %1}, %2;" : "=f"(lo), "=f"(hi) : "l"(v));
    return make_float2(lo, hi);
}
__device__ __forceinline__ u64 dup2(float x) { return pk(x, x); }

// Degree-6 polynomial G(u) ~= (1-u)/(1+u) on u in [0,1] (Chebyshev-truncated,
// max abs err ~3.6e-5). tanh(|x|) = G(exp(-2|x|)); sign applied via bit ops.
#define G0c 0.999956458f
#define G1c -1.996579368f
#define G2c 1.952699598f
#define G3c -1.733862064f
#define G4c 1.203783808f
#define G5c -0.533660512f
#define G6c 0.10766208f

#define TWO_LOG2E 2.8853900817779268f   // 2*log2(e)

// K0: transpose W [H][F] -> g_WT [F][H]  (one-time, tiny)
__global__ void k_transpose_W(const float* __restrict__ W) {
    int t = blockIdx.x * blockDim.x + threadIdx.x;
    if (t < NF * NH) {
        int h = t >> 8;          // t / NF
        int f = t & (NF - 1);    // t % NF
        g_WT[f * NH + h] = W[t];
    }
}

// K1: projection. Block b < NQ handles qs[b], else hs[b-NQ].
// Computes dst[h][l] = sum_f x[l][f] * W[h][f] + bias[h], stored h-major.
__global__ __launch_bounds__(256) void k_project(const float* __restrict__ qs,
                                                 const float* __restrict__ hs,
                                                 const float* __restrict__ bias) {
    extern __shared__ float sm[];
    float* xs = sm;              // [NL][NF]
    float* wT = sm + NL * NF;    // [NF][NH]
    const int b = blockIdx.x;
    const int t = threadIdx.x;
    const float* x = (b < NQ) ? (qs + (size_t)b * NL * NF)
                              : (hs + (size_t)(b - NQ) * NL * NF);
    float* dst = (b < NQ) ? (g_WqT + (size_t)b * NH * NL)
                          : (g_WhT + (size_t)(b - NQ) * NH * NL);

    {
        const float4* xg = reinterpret_cast<const float4*>(x);
        float4* xs4 = reinterpret_cast<float4*>(xs);
        for (int e = t; e < NL * NF / 4; e += 256) xs4[e] = xg[e];
        const float4* wg = reinterpret_cast<const float4*>(g_WT);
        float4* ws4 = reinterpret_cast<float4*>(wT);
        for (int e = t; e < NF * NH / 4; e += 256) ws4[e] = wg[e];
    }
    __syncthreads();

    const int h0 = 4 * (t & 15);   // wT loads coalesced over h
    const int l0 = 4 * (t >> 4);   // xs loads broadcast
    float acc[4][4];
    #pragma unroll
    for (int c = 0; c < 4; c++)
        #pragma unroll
        for (int r = 0; r < 4; r++) acc[c][r] = 0.f;

    for (int f = 0; f < NF; f += 4) {
        float xv[4][4];
        #pragma unroll
        for (int r = 0; r < 4; r++) {
            float4 v = *reinterpret_cast<const float4*>(&xs[(l0 + r) * NF + f]);
            xv[r][0] = v.x; xv[r][1] = v.y; xv[r][2] = v.z; xv[r][3] = v.w;
        }
        #pragma unroll
        for (int i = 0; i < 4; i++) {
            float4 w = *reinterpret_cast<const float4*>(&wT[(f + i) * NH + h0]);
            float wv[4] = {w.x, w.y, w.z, w.w};
            #pragma unroll
            for (int c = 0; c < 4; c++)
                #pragma unroll
                for (int r = 0; r < 4; r++)
                    acc[c][r] = fmaf(wv[c], xv[r][i], acc[c][r]);
        }
    }
    #pragma unroll
    for (int c = 0; c < 4; c++) {
        float bb = __ldg(&bias[h0 + c]);
        float4 v = make_float4(acc[c][0] + bb, acc[c][1] + bb,
                               acc[c][2] + bb, acc[c][3] + bb);
        *reinterpret_cast<float4*>(&dst[(h0 + c) * NL + l0]) = v;
    }
}

// K2: fused scores(tanh) -> softmax -> att @ hs, one block per (q, s).
__global__ __launch_bounds__(256) void k_attn(const float* __restrict__ hs,
                                              float* __restrict__ out) {
    extern __shared__ float sm[];
    float* wqT = sm;                 // [NH][NL]  (prescaled by 2*log2e)
    float* whT = sm + NH * NL;       // [NH][NL]
    float* hss = sm + 2 * NH * NL;   // [NL][NF]
    float* attT = sm;                // overlay over wqT: [j][i] stride NL

    const int s = blockIdx.x;
    const int q = blockIdx.y;
    const int t = threadIdx.x;

    {
        const float4* a = reinterpret_cast<const float4*>(g_WqT + (size_t)q * NH * NL);
        const float4* b = reinterpret_cast<const float4*>(g_WhT + (size_t)s * NH * NL);
        const float4* c = reinterpret_cast<const float4*>(hs + (size_t)s * NL * NF);
        float4* w1 = reinterpret_cast<float4*>(wqT);
        float4* w2 = reinterpret_cast<float4*>(whT);
        float4* w3 = reinterpret_cast<float4*>(hss);
        for (int e = t; e < NH * NL / 4; e += 256) {
            float4 av = a[e];
            av.x *= TWO_LOG2E; av.y *= TWO_LOG2E; av.z *= TWO_LOG2E; av.w *= TWO_LOG2E;
            w1[e] = av;
            w2[e] = b[e];
        }
        for (int e = t; e < NL * NF / 4; e += 256) w3[e] = c[e];
    }
    __syncthreads();

    const int i0 = 4 * (t >> 4);   // query rows (broadcast loads)
    const int j0 = 4 * (t & 15);   // support cols (coalesced loads)

    const u64 SGN2 = 0x8000000080000000ull;
    const u64 G0 = dup2(G0c), G1 = dup2(G1c), G2 = dup2(G2c), G3 = dup2(G3c),
              G4 = dup2(G4c), G5 = dup2(G5c), G6 = dup2(G6c);

    // Phase A: scores[i0+r][j0+2cc+{0,1}] = sum_h tanh(wq[i][h]*wh[j][h]), packed pairs
    u64 accp[4][2];
    #pragma unroll
    for (int r = 0; r < 4; r++) { accp[r][0] = 0ull; accp[r][1] = 0ull; }

    #pragma unroll 2
    for (int h = 0; h < NH; h++) {
        float4 a4 = *reinterpret_cast<const float4*>(&wqT[h * NL + i0]);  // prescaled
        ulonglong2 b2 = *reinterpret_cast<const ulonglong2*>(&whT[h * NL + j0]);
        u64 ad[4] = {pk(a4.x, a4.x), pk(a4.y, a4.y), pk(a4.z, a4.z), pk(a4.w, a4.w)};
        u64 bp[2] = {b2.x, b2.y};
        #pragma unroll
        for (int r = 0; r < 4; r++) {
            #pragma unroll
            for (int cc = 0; cc < 2; cc++) {
                u64 p = f2mul(ad[r], bp[cc]);           // 2*log2e * x, both halves
                float2 pf = upk(p);
                float ulo = fast_ex2(-fabsf(pf.x));     // u = 2^(-|.|) in (0,1]
                float uhi = fast_ex2(-fabsf(pf.y));
                u64 u = pk(ulo, uhi);
                u64 g = f2fma(u, G6, G5);               // Horner, degree 6
                g = f2fma(u, g, G4);
                g = f2fma(u, g, G3);
                g = f2fma(u, g, G2);
                g = f2fma(u, g, G1);
                g = f2fma(u, g, G0);                    // = tanh(|x|) >= 0
                g ^= (p & SGN2);                        // apply sign(x) (2x LOP3)
                accp[r][cc] = f2add(accp[r][cc], g);
            }
        }
    }

    // Phase B: softmax over j for each row. Rows live across 16-lane groups.
    float accs[4][4];
    float inv[4];
    #pragma unroll
    for (int r = 0; r < 4; r++) {
        float2 x0 = upk(accp[r][0]);
        float2 x1 = upk(accp[r][1]);
        accs[r][0] = x0.x; accs[r][1] = x0.y; accs[r][2] = x1.x; accs[r][3] = x1.y;
        float m = fmaxf(fmaxf(accs[r][0], accs[r][1]), fmaxf(accs[r][2], accs[r][3]));
        #pragma unroll
        for (int d = 1; d < 16; d <<= 1)
            m = fmaxf(m, __shfl_xor_sync(0xffffffffu, m, d));
        float ssum = 0.f;
        #pragma unroll
        for (int c = 0; c < 4; c++) {
            float e = fast_ex2((accs[r][c] - m) * 1.4426950408889634f);
            accs[r][c] = e;
            ssum += e;
        }
        #pragma unroll
        for (int d = 1; d < 16; d <<= 1)
            ssum += __shfl_xor_sync(0xffffffffu, ssum, d);
        inv[r] = fast_rcp(ssum);
    }

    __syncthreads();  // all phase-A reads of wqT/whT done before overlay write
    #pragma unroll
    for (int c = 0; c < 4; c++)
        #pragma unroll
        for (int r = 0; r < 4; r++)
            attT[(j0 + c) * NL + (i0 + r)] = accs[r][c] * inv[r];
    __syncthreads();

    // Phase C: out[i][f] = sum_j att[i][j] * hs[j][f]   (packed f32x2 FMAs)
    float* op = out + (size_t)((q * NS + s) * NL) * NF;
    #pragma unroll
    for (int p4 = 0; p4 < 4; p4++) {
        const int fb = 4 * (t & 15) + 64 * p4;
        u64 o[4][2];
        #pragma unroll
        for (int r = 0; r < 4; r++) { o[r][0] = 0ull; o[r][1] = 0ull; }
        #pragma unroll 4
        for (int j = 0; j < NL; j++) {
            float4 a4 = *reinterpret_cast<const float4*>(&attT[j * NL + i0]);
            ulonglong2 h2 = *reinterpret_cast<const ulonglong2*>(&hss[j * NF + fb]);
            u64 d0 = pk(a4.x, a4.x), d1 = pk(a4.y, a4.y),
                d2 = pk(a4.z, a4.z), d3 = pk(a4.w, a4.w);
            o[0][0] = f2fma(d0, h2.x, o[0][0]); o[0][1] = f2fma(d0, h2.y, o[0][1]);
            o[1][0] = f2fma(d1, h2.x, o[1][0]); o[1][1] = f2fma(d1, h2.y, o[1][1]);
            o[2][0] = f2fma(d2, h2.x, o[2][0]); o[2][1] = f2fma(d2, h2.y, o[2][1]);
            o[3][0] = f2fma(d3, h2.x, o[3][0]); o[3][1] = f2fma(d3, h2.y, o[3][1]);
        }
        #pragma unroll
        for (int r = 0; r < 4; r++) {
            ulonglong2 v; v.x = o[r][0]; v.y = o[r][1];
            *reinterpret_cast<ulonglong2*>(&op[(i0 + r) * NF + fb]) = v;
        }
    }
}

extern "C" void kernel_launch(void* const* d_in, const int* in_sizes, int n_in,
                              void* d_out, int out_size) {
    const float* qs = (const float*)d_in[0];
    const float* hs = (const float*)d_in[1];
    const float* W  = (const float*)d_in[2];
    const float* b  = (const float*)d_in[3];
    float* out = (float*)d_out;

    const int smem_proj = (NL * NF + NF * NH) * (int)sizeof(float);     // 128 KB
    const int smem_attn = (2 * NH * NL + NL * NF) * (int)sizeof(float); // 96 KB
    cudaFuncSetAttribute(k_project, cudaFuncAttributeMaxDynamicSharedMemorySize, smem_proj);
    cudaFuncSetAttribute(k_attn, cudaFuncAttributeMaxDynamicSharedMemorySize, smem_attn);

    k_transpose_W<<<64, 256>>>(W);
    k_project<<<NQ + NS, 256, smem_proj>>>(qs, hs, b);
    k_attn<<<dim3(NS, NQ), 256, smem_attn>>>(hs, out);
}